// round 1
// baseline (speedup 1.0000x reference)
#include <cuda_runtime.h>
#include <math.h>

#define B_SZ 2
#define SEQ  1024
#define DM   1024
#define DI   2048
#define DS   16
#define DFF  4096
#define MTOK (B_SZ*SEQ)

// ---------------- scratch (device globals; allocation-free) ----------------
__device__ float g_xn   [MTOK*DM];        // 8 MB
__device__ float g_xg   [MTOK*2*DI];      // 32 MB  (x_proj | gate)
__device__ float g_xc   [MTOK*DI];        // 16 MB
__device__ float g_delta[MTOK*DI];        // 16 MB
__device__ float g_Bm   [67108864];       // 256 MB  MTOK*DI*DS
__device__ float g_Cm   [67108864];       // 256 MB
__device__ float g_y    [MTOK*DI];        // 16 MB
__device__ float g_x2   [MTOK*DM];        // 8 MB
__device__ float g_xn2  [MTOK*DM];        // 8 MB
__device__ float g_h1   [MTOK*DFF];       // 32 MB

// ---------------- LayerNorm: one block per row of 1024 ----------------
__global__ __launch_bounds__(256)
void ln_kernel(const float* __restrict__ in, const float* __restrict__ g,
               const float* __restrict__ bcoef, float* __restrict__ out)
{
    int row = blockIdx.x;
    int tid = threadIdx.x;                        // 256 threads, 4 floats each
    float4 v = ((const float4*)(in + (size_t)row*DM))[tid];

    __shared__ float red1[8];
    __shared__ float red2[8];

    float s = v.x + v.y + v.z + v.w;
    #pragma unroll
    for (int o = 16; o > 0; o >>= 1) s += __shfl_xor_sync(0xffffffffu, s, o);
    if ((tid & 31) == 0) red1[tid >> 5] = s;
    __syncthreads();
    float tot = 0.f;
    #pragma unroll
    for (int i = 0; i < 8; i++) tot += red1[i];
    float mean = tot * (1.0f / DM);

    float dx = v.x - mean, dy = v.y - mean, dz = v.z - mean, dw = v.w - mean;
    float sq = dx*dx + dy*dy + dz*dz + dw*dw;
    #pragma unroll
    for (int o = 16; o > 0; o >>= 1) sq += __shfl_xor_sync(0xffffffffu, sq, o);
    if ((tid & 31) == 0) red2[tid >> 5] = sq;
    __syncthreads();
    float tot2 = 0.f;
    #pragma unroll
    for (int i = 0; i < 8; i++) tot2 += red2[i];
    float rstd = rsqrtf(tot2 * (1.0f / DM) + 1e-5f);

    float4 gg = ((const float4*)g)[tid];
    float4 bb = ((const float4*)bcoef)[tid];
    float4 o4;
    o4.x = dx * rstd * gg.x + bb.x;
    o4.y = dy * rstd * gg.y + bb.y;
    o4.z = dz * rstd * gg.z + bb.z;
    o4.w = dw * rstd * gg.w + bb.w;
    ((float4*)(out + (size_t)row*DM))[tid] = o4;
}

// ---------------- SGEMM: C[M,N] = A[M,K] @ W[K,N], fused epilogue ----------------
// EPI: 0 = +bias ; 1 = delta = sigmoid(+bias)*0.099+0.001 ; 2 = gelu(+bias, exact) ;
//      3 = +bias + add[r*N+c]
template<int EPI>
__global__ __launch_bounds__(256)
void sgemm(int M, int N, int K,
           const float* __restrict__ A, const float* __restrict__ Bw,
           const float* __restrict__ bias, const float* __restrict__ add,
           float* __restrict__ C)
{
    const int BM = 128, BN = 128, BK = 8, TM = 8, TN = 8;
    __shared__ float As[BK][BM];
    __shared__ float Bs[BK][BN];

    int tid  = threadIdx.x;
    int crow = blockIdx.y * BM;
    int ccol = blockIdx.x * BN;

    int arow = tid >> 1;              // 0..127
    int acol = (tid & 1) * 4;         // 0 or 4
    int brow = tid >> 5;              // 0..7
    int bcol = (tid & 31) * 4;        // 0..124

    const float* Ab = A  + (size_t)crow * K;
    const float* Bb = Bw + ccol;

    float acc[TM][TN] = {};
    float ra[TM], rb[TN];
    int ty = tid >> 4, tx = tid & 15;

    for (int k0 = 0; k0 < K; k0 += BK) {
        float4 av = *(const float4*)(Ab + (size_t)arow * K + k0 + acol);
        As[acol + 0][arow] = av.x;
        As[acol + 1][arow] = av.y;
        As[acol + 2][arow] = av.z;
        As[acol + 3][arow] = av.w;
        float4 bv = *(const float4*)(Bb + (size_t)(k0 + brow) * N + bcol);
        *(float4*)(&Bs[brow][bcol]) = bv;
        __syncthreads();

        #pragma unroll
        for (int k = 0; k < BK; ++k) {
            #pragma unroll
            for (int i = 0; i < TM; i += 4) *(float4*)(ra + i) = *(const float4*)(&As[k][ty*TM + i]);
            #pragma unroll
            for (int j = 0; j < TN; j += 4) *(float4*)(rb + j) = *(const float4*)(&Bs[k][tx*TN + j]);
            #pragma unroll
            for (int i = 0; i < TM; i++)
                #pragma unroll
                for (int j = 0; j < TN; j++)
                    acc[i][j] += ra[i] * rb[j];
        }
        __syncthreads();
    }

    #pragma unroll
    for (int i = 0; i < TM; i++) {
        int r = crow + ty*TM + i;
        #pragma unroll
        for (int j = 0; j < TN; j += 4) {
            int c = ccol + tx*TN + j;
            float4 o;
            float vv[4];
            #pragma unroll
            for (int q = 0; q < 4; q++) {
                float v = acc[i][j+q] + bias[c+q];
                if (EPI == 1) v = 1.0f/(1.0f + expf(-v)) * 0.099f + 0.001f;
                if (EPI == 2) v = 0.5f * v * (1.0f + erff(v * 0.70710678118654752f));
                if (EPI == 3) v += add[(size_t)r * N + c + q];
                vv[q] = v;
            }
            o.x = vv[0]; o.y = vv[1]; o.z = vv[2]; o.w = vv[3];
            *(float4*)(&C[(size_t)r * N + c]) = o;
        }
    }
}

// ---------------- causal depthwise conv (taps=4) ----------------
__global__ __launch_bounds__(256)
void conv_kernel(const float* __restrict__ xg, const float* __restrict__ cw,
                 const float* __restrict__ cb, float* __restrict__ xc)
{
    int idx   = blockIdx.x * blockDim.x + threadIdx.x;   // over MTOK*DI
    int d     = idx & (DI - 1);
    int token = idx >> 11;
    int t     = token & (SEQ - 1);
    float acc = cb[d];
    #pragma unroll
    for (int k = 0; k < 4; k++) {
        int ts = t - 3 + k;
        if (ts >= 0) acc += xg[(size_t)(token - 3 + k) * (2*DI) + d] * cw[d*4 + k];
    }
    xc[idx] = acc;
}

// ---------------- selective scan: one thread per (b,d,n) ----------------
__global__ __launch_bounds__(256)
void scan_kernel(const float* __restrict__ xg, const float* __restrict__ delta,
                 const float* __restrict__ Bm, const float* __restrict__ Cm,
                 const float* __restrict__ A_log, const float* __restrict__ Dp,
                 float* __restrict__ y)
{
    int tid = blockIdx.x * blockDim.x + threadIdx.x;     // 65536
    int n = tid & (DS - 1);
    int d = (tid >> 4) & (DI - 1);
    int b = tid >> 15;

    float Aneg = -expf(A_log[d*DS + n]);
    float Dval = Dp[d];
    float h = 0.f;
    int base_tok = b * SEQ;

    for (int t = 0; t < SEQ; ++t) {
        int token = base_tok + t;
        float dv = delta[(size_t)token * DI + d];
        float xp = xg[(size_t)token * (2*DI) + d];
        float bm = Bm[(size_t)token * (DI*DS) + d*DS + n];
        float cm = Cm[(size_t)token * (DI*DS) + d*DS + n];
        float a  = __expf(dv * Aneg);
        h = a * h + (dv * bm) * xp;
        float yv = cm * h;
        yv += __shfl_xor_sync(0xffffffffu, yv, 1);
        yv += __shfl_xor_sync(0xffffffffu, yv, 2);
        yv += __shfl_xor_sync(0xffffffffu, yv, 4);
        yv += __shfl_xor_sync(0xffffffffu, yv, 8);
        if (n == 0) {
            float g  = xg[(size_t)token * (2*DI) + DI + d];
            float sg = g / (1.0f + __expf(-g));               // silu(gate)
            y[(size_t)token * DI + d] = (yv + Dval * xp) * sg;
        }
    }
}

// ---------------- host launcher ----------------
extern "C" void kernel_launch(void* const* d_in, const int* in_sizes, int n_in,
                              void* d_out, int out_size)
{
    const float* x      = (const float*)d_in[0];
    const float* ln1_g  = (const float*)d_in[1];
    const float* ln1_b  = (const float*)d_in[2];
    const float* W_in   = (const float*)d_in[3];
    const float* b_in   = (const float*)d_in[4];
    const float* conv_w = (const float*)d_in[5];
    const float* conv_b = (const float*)d_in[6];
    const float* A_log  = (const float*)d_in[7];
    const float* W_B    = (const float*)d_in[8];
    const float* b_B    = (const float*)d_in[9];
    const float* W_C    = (const float*)d_in[10];
    const float* b_C    = (const float*)d_in[11];
    const float* Dp     = (const float*)d_in[12];
    const float* W_dt   = (const float*)d_in[13];
    const float* b_dt   = (const float*)d_in[14];
    const float* W_out  = (const float*)d_in[15];
    const float* b_out  = (const float*)d_in[16];
    const float* ln2_g  = (const float*)d_in[17];
    const float* ln2_b  = (const float*)d_in[18];
    const float* W1     = (const float*)d_in[19];
    const float* b1     = (const float*)d_in[20];
    const float* W2     = (const float*)d_in[21];
    const float* b2     = (const float*)d_in[22];
    float* out = (float*)d_out;

    float *xn, *xg, *xc, *delta, *Bm, *Cm, *y, *x2, *xn2, *h1;
    cudaGetSymbolAddress((void**)&xn,    g_xn);
    cudaGetSymbolAddress((void**)&xg,    g_xg);
    cudaGetSymbolAddress((void**)&xc,    g_xc);
    cudaGetSymbolAddress((void**)&delta, g_delta);
    cudaGetSymbolAddress((void**)&Bm,    g_Bm);
    cudaGetSymbolAddress((void**)&Cm,    g_Cm);
    cudaGetSymbolAddress((void**)&y,     g_y);
    cudaGetSymbolAddress((void**)&x2,    g_x2);
    cudaGetSymbolAddress((void**)&xn2,   g_xn2);
    cudaGetSymbolAddress((void**)&h1,    g_h1);

    // 1) LN1
    ln_kernel<<<MTOK, 256>>>(x, ln1_g, ln1_b, xn);
    // 2) xg = xn @ W_in + b_in              [2048, 4096]
    sgemm<0><<<dim3((2*DI)/128, MTOK/128), 256>>>(MTOK, 2*DI, DM, xn, W_in, b_in, nullptr, xg);
    // 3) causal depthwise conv on x_proj    [2048, 2048]
    conv_kernel<<<(MTOK*DI)/256, 256>>>(xg, conv_w, conv_b, xc);
    // 4) delta = sigmoid(xc @ W_dt + b_dt)*0.099 + 0.001
    sgemm<1><<<dim3(DI/128, MTOK/128), 256>>>(MTOK, DI, DI, xc, W_dt, b_dt, nullptr, delta);
    // 5) Bm, Cm                             [2048, 32768] each
    sgemm<0><<<dim3((DI*DS)/128, MTOK/128), 256>>>(MTOK, DI*DS, DI, xc, W_B, b_B, nullptr, Bm);
    sgemm<0><<<dim3((DI*DS)/128, MTOK/128), 256>>>(MTOK, DI*DS, DI, xc, W_C, b_C, nullptr, Cm);
    // 6) selective scan + Dp*x_proj + silu(gate) fused
    scan_kernel<<<256, 256>>>(xg, delta, Bm, Cm, A_log, Dp, y);
    // 7) x2 = residual + y @ W_out + b_out
    sgemm<3><<<dim3(DM/128, MTOK/128), 256>>>(MTOK, DM, DI, y, W_out, b_out, x, x2);
    // 8) LN2
    ln_kernel<<<MTOK, 256>>>(x2, ln2_g, ln2_b, xn2);
    // 9) h1 = gelu(xn2 @ W1 + b1)
    sgemm<2><<<dim3(DFF/128, MTOK/128), 256>>>(MTOK, DFF, DM, xn2, W1, b1, nullptr, h1);
    // 10) out = x2 + h1 @ W2 + b2
    sgemm<3><<<dim3(DM/128, MTOK/128), 256>>>(MTOK, DM, DFF, h1, W2, b2, x2, out);
}

// round 2
// speedup vs baseline: 1.0065x; 1.0065x over previous
#include <cuda_runtime.h>
#include <math.h>

#define B_SZ 2
#define SEQ  1024
#define DM   1024
#define DI   2048
#define DS   16
#define DFF  4096
#define MTOK (B_SZ*SEQ)

// ---------------- scratch (device globals; allocation-free) ----------------
__device__ float g_xn   [MTOK*DM];        // 8 MB
__device__ float g_xg   [MTOK*2*DI];      // 32 MB  (x_proj | gate)
__device__ float g_xc   [MTOK*DI];        // 16 MB
__device__ float g_delta[MTOK*DI];        // 16 MB
__device__ float g_Bm   [67108864];       // 256 MB  MTOK*DI*DS
__device__ float g_Cm   [67108864];       // 256 MB
__device__ float g_y    [MTOK*DI];        // 16 MB
__device__ float g_x2   [MTOK*DM];        // 8 MB
__device__ float g_xn2  [MTOK*DM];        // 8 MB
__device__ float g_h1   [MTOK*DFF];       // 32 MB

// ---------------- LayerNorm: one block per row of 1024 ----------------
__global__ __launch_bounds__(256)
void ln_kernel(const float* __restrict__ in, const float* __restrict__ g,
               const float* __restrict__ bcoef, float* __restrict__ out)
{
    int row = blockIdx.x;
    int tid = threadIdx.x;                        // 256 threads, 4 floats each
    float4 v = ((const float4*)(in + (size_t)row*DM))[tid];

    __shared__ float red1[8];
    __shared__ float red2[8];

    float s = v.x + v.y + v.z + v.w;
    #pragma unroll
    for (int o = 16; o > 0; o >>= 1) s += __shfl_xor_sync(0xffffffffu, s, o);
    if ((tid & 31) == 0) red1[tid >> 5] = s;
    __syncthreads();
    float tot = 0.f;
    #pragma unroll
    for (int i = 0; i < 8; i++) tot += red1[i];
    float mean = tot * (1.0f / DM);

    float dx = v.x - mean, dy = v.y - mean, dz = v.z - mean, dw = v.w - mean;
    float sq = dx*dx + dy*dy + dz*dz + dw*dw;
    #pragma unroll
    for (int o = 16; o > 0; o >>= 1) sq += __shfl_xor_sync(0xffffffffu, sq, o);
    if ((tid & 31) == 0) red2[tid >> 5] = sq;
    __syncthreads();
    float tot2 = 0.f;
    #pragma unroll
    for (int i = 0; i < 8; i++) tot2 += red2[i];
    float rstd = rsqrtf(tot2 * (1.0f / DM) + 1e-5f);

    float4 gg = ((const float4*)g)[tid];
    float4 bb = ((const float4*)bcoef)[tid];
    float4 o4;
    o4.x = dx * rstd * gg.x + bb.x;
    o4.y = dy * rstd * gg.y + bb.y;
    o4.z = dz * rstd * gg.z + bb.z;
    o4.w = dw * rstd * gg.w + bb.w;
    ((float4*)(out + (size_t)row*DM))[tid] = o4;
}

// ---------------- SGEMM: C[M,N] = A[M,K] @ W[K,N], fused epilogue ----------------
// EPI: 0 = +bias ; 1 = delta = sigmoid(+bias)*0.099+0.001 ; 2 = gelu(+bias, exact) ;
//      3 = +bias + add[r*N+c]
template<int EPI>
__global__ __launch_bounds__(256)
void sgemm(int M, int N, int K,
           const float* __restrict__ A, const float* __restrict__ Bw,
           const float* __restrict__ bias, const float* __restrict__ add,
           float* __restrict__ C)
{
    const int BM = 128, BN = 128, BK = 8, TM = 8, TN = 8;
    __shared__ float As[BK][BM];
    __shared__ float Bs[BK][BN];

    int tid  = threadIdx.x;
    int crow = blockIdx.y * BM;
    int ccol = blockIdx.x * BN;

    int arow = tid >> 1;              // 0..127
    int acol = (tid & 1) * 4;         // 0 or 4
    int brow = tid >> 5;              // 0..7
    int bcol = (tid & 31) * 4;        // 0..124

    const float* Ab = A  + (size_t)crow * K;
    const float* Bb = Bw + ccol;

    float acc[TM][TN] = {};
    float ra[TM], rb[TN];
    int ty = tid >> 4, tx = tid & 15;

    for (int k0 = 0; k0 < K; k0 += BK) {
        float4 av = *(const float4*)(Ab + (size_t)arow * K + k0 + acol);
        As[acol + 0][arow] = av.x;
        As[acol + 1][arow] = av.y;
        As[acol + 2][arow] = av.z;
        As[acol + 3][arow] = av.w;
        float4 bv = *(const float4*)(Bb + (size_t)(k0 + brow) * N + bcol);
        *(float4*)(&Bs[brow][bcol]) = bv;
        __syncthreads();

        #pragma unroll
        for (int k = 0; k < BK; ++k) {
            #pragma unroll
            for (int i = 0; i < TM; i += 4) *(float4*)(ra + i) = *(const float4*)(&As[k][ty*TM + i]);
            #pragma unroll
            for (int j = 0; j < TN; j += 4) *(float4*)(rb + j) = *(const float4*)(&Bs[k][tx*TN + j]);
            #pragma unroll
            for (int i = 0; i < TM; i++)
                #pragma unroll
                for (int j = 0; j < TN; j++)
                    acc[i][j] += ra[i] * rb[j];
        }
        __syncthreads();
    }

    #pragma unroll
    for (int i = 0; i < TM; i++) {
        int r = crow + ty*TM + i;
        #pragma unroll
        for (int j = 0; j < TN; j += 4) {
            int c = ccol + tx*TN + j;
            float4 o;
            float vv[4];
            #pragma unroll
            for (int q = 0; q < 4; q++) {
                float v = acc[i][j+q] + bias[c+q];
                if (EPI == 1) v = 1.0f/(1.0f + expf(-v)) * 0.099f + 0.001f;
                if (EPI == 2) v = 0.5f * v * (1.0f + erff(v * 0.70710678118654752f));
                if (EPI == 3) v += add[(size_t)r * N + c + q];
                vv[q] = v;
            }
            o.x = vv[0]; o.y = vv[1]; o.z = vv[2]; o.w = vv[3];
            *(float4*)(&C[(size_t)r * N + c]) = o;
        }
    }
}

// ---------------- causal depthwise conv (taps=4) ----------------
__global__ __launch_bounds__(256)
void conv_kernel(const float* __restrict__ xg, const float* __restrict__ cw,
                 const float* __restrict__ cb, float* __restrict__ xc)
{
    int idx   = blockIdx.x * blockDim.x + threadIdx.x;   // over MTOK*DI
    int d     = idx & (DI - 1);
    int token = idx >> 11;
    int t     = token & (SEQ - 1);
    float acc = cb[d];
    #pragma unroll
    for (int k = 0; k < 4; k++) {
        int ts = t - 3 + k;
        if (ts >= 0) acc += xg[(size_t)(token - 3 + k) * (2*DI) + d] * cw[d*4 + k];
    }
    xc[idx] = acc;
}

// ---------------- selective scan: one thread per (b,d,n) ----------------
__global__ __launch_bounds__(256)
void scan_kernel(const float* __restrict__ xg, const float* __restrict__ delta,
                 const float* __restrict__ Bm, const float* __restrict__ Cm,
                 const float* __restrict__ A_log, const float* __restrict__ Dp,
                 float* __restrict__ y)
{
    int tid = blockIdx.x * blockDim.x + threadIdx.x;     // 65536
    int n = tid & (DS - 1);
    int d = (tid >> 4) & (DI - 1);
    int b = tid >> 15;

    float Aneg = -expf(A_log[d*DS + n]);
    float Dval = Dp[d];
    float h = 0.f;
    int base_tok = b * SEQ;

    for (int t = 0; t < SEQ; ++t) {
        int token = base_tok + t;
        float dv = delta[(size_t)token * DI + d];
        float xp = xg[(size_t)token * (2*DI) + d];
        float bm = Bm[(size_t)token * (DI*DS) + d*DS + n];
        float cm = Cm[(size_t)token * (DI*DS) + d*DS + n];
        float a  = __expf(dv * Aneg);
        h = a * h + (dv * bm) * xp;
        float yv = cm * h;
        yv += __shfl_xor_sync(0xffffffffu, yv, 1);
        yv += __shfl_xor_sync(0xffffffffu, yv, 2);
        yv += __shfl_xor_sync(0xffffffffu, yv, 4);
        yv += __shfl_xor_sync(0xffffffffu, yv, 8);
        if (n == 0) {
            float g  = xg[(size_t)token * (2*DI) + DI + d];
            float sg = g / (1.0f + __expf(-g));               // silu(gate)
            y[(size_t)token * DI + d] = (yv + Dval * xp) * sg;
        }
    }
}

// ---------------- host launcher ----------------
extern "C" void kernel_launch(void* const* d_in, const int* in_sizes, int n_in,
                              void* d_out, int out_size)
{
    const float* x      = (const float*)d_in[0];
    const float* ln1_g  = (const float*)d_in[1];
    const float* ln1_b  = (const float*)d_in[2];
    const float* W_in   = (const float*)d_in[3];
    const float* b_in   = (const float*)d_in[4];
    const float* conv_w = (const float*)d_in[5];
    const float* conv_b = (const float*)d_in[6];
    const float* A_log  = (const float*)d_in[7];
    const float* W_B    = (const float*)d_in[8];
    const float* b_B    = (const float*)d_in[9];
    const float* W_C    = (const float*)d_in[10];
    const float* b_C    = (const float*)d_in[11];
    const float* Dp     = (const float*)d_in[12];
    const float* W_dt   = (const float*)d_in[13];
    const float* b_dt   = (const float*)d_in[14];
    const float* W_out  = (const float*)d_in[15];
    const float* b_out  = (const float*)d_in[16];
    const float* ln2_g  = (const float*)d_in[17];
    const float* ln2_b  = (const float*)d_in[18];
    const float* W1     = (const float*)d_in[19];
    const float* b1     = (const float*)d_in[20];
    const float* W2     = (const float*)d_in[21];
    const float* b2     = (const float*)d_in[22];
    float* out = (float*)d_out;

    float *xn, *xg, *xc, *delta, *Bm, *Cm, *y, *x2, *xn2, *h1;
    cudaGetSymbolAddress((void**)&xn,    g_xn);
    cudaGetSymbolAddress((void**)&xg,    g_xg);
    cudaGetSymbolAddress((void**)&xc,    g_xc);
    cudaGetSymbolAddress((void**)&delta, g_delta);
    cudaGetSymbolAddress((void**)&Bm,    g_Bm);
    cudaGetSymbolAddress((void**)&Cm,    g_Cm);
    cudaGetSymbolAddress((void**)&y,     g_y);
    cudaGetSymbolAddress((void**)&x2,    g_x2);
    cudaGetSymbolAddress((void**)&xn2,   g_xn2);
    cudaGetSymbolAddress((void**)&h1,    g_h1);

    // 1) LN1
    ln_kernel<<<MTOK, 256>>>(x, ln1_g, ln1_b, xn);
    // 2) xg = xn @ W_in + b_in              [2048, 4096]
    sgemm<0><<<dim3((2*DI)/128, MTOK/128), 256>>>(MTOK, 2*DI, DM, xn, W_in, b_in, nullptr, xg);
    // 3) causal depthwise conv on x_proj    [2048, 2048]
    conv_kernel<<<(MTOK*DI)/256, 256>>>(xg, conv_w, conv_b, xc);
    // 4) delta = sigmoid(xc @ W_dt + b_dt)*0.099 + 0.001
    sgemm<1><<<dim3(DI/128, MTOK/128), 256>>>(MTOK, DI, DI, xc, W_dt, b_dt, nullptr, delta);
    // 5) Bm, Cm                             [2048, 32768] each
    sgemm<0><<<dim3((DI*DS)/128, MTOK/128), 256>>>(MTOK, DI*DS, DI, xc, W_B, b_B, nullptr, Bm);
    sgemm<0><<<dim3((DI*DS)/128, MTOK/128), 256>>>(MTOK, DI*DS, DI, xc, W_C, b_C, nullptr, Cm);
    // 6) selective scan + Dp*x_proj + silu(gate) fused
    scan_kernel<<<256, 256>>>(xg, delta, Bm, Cm, A_log, Dp, y);
    // 7) x2 = residual + y @ W_out + b_out
    sgemm<3><<<dim3(DM/128, MTOK/128), 256>>>(MTOK, DM, DI, y, W_out, b_out, x, x2);
    // 8) LN2
    ln_kernel<<<MTOK, 256>>>(x2, ln2_g, ln2_b, xn2);
    // 9) h1 = gelu(xn2 @ W1 + b1)
    sgemm<2><<<dim3(DFF/128, MTOK/128), 256>>>(MTOK, DFF, DM, xn2, W1, b1, nullptr, h1);
    // 10) out = x2 + h1 @ W2 + b2
    sgemm<3><<<dim3(DM/128, MTOK/128), 256>>>(MTOK, DM, DFF, h1, W2, b2, x2, out);
}